// round 7
// baseline (speedup 1.0000x reference)
#include <cuda_runtime.h>
#include <math.h>

#define T_SNAP 4
#define EQ     4096
#define NNODES 8192
#define H      32
#define BCAP   32                // in-edge bucket capacity per (t, node)
#define RCAP   128               // per-query reach-set capacity
#define HT     16384             // global hash table slots (power of 2)
#define NB     (EQ * 3)          // pooled nodes (GRU batch)
#define BW     256               // bitmap words per reach set (8192 bits)

#define GRID1  296               // 2 blocks/SM, all-resident
#define BLK1   256
#define WPB1   (BLK1 / 32)
#define NWARP1 (GRID1 * WPB1)

#define GRID2  296
#define BLK2   128
#define NTH2   (GRID2 * BLK2)
#define NWARP2 (GRID2 * (BLK2 / 32))

// Scratch (static device globals, zero-initialized; every call restores zeros)
__device__ int    g_bcnt[T_SNAP * NNODES];
__device__ int    g_bsrc[T_SNAP * NNODES * BCAP];
__device__ float  g_tops[T_SNAP * EQ * 3];
__device__ float  g_gi[256 * 3 * H];       // gi(v): 256 degrees x (3H), bih folded
__device__ int    g_htkey[HT];             // 0 = empty
__device__ float4 g_slotv[HT];
__device__ float  g_uh[HT * H];
__device__ int    g_bslot[NB];
__device__ int    g_uniq[NB];
__device__ int    g_uniq_cnt;
__device__ int    g_cnt1, g_cnt2, g_cnt3;          // barrier arrive counters
__device__ volatile int g_flag1, g_flag2, g_flag3; // barrier release flags

// flag-based grid barrier: one atomic per block, plain-load polling
__device__ __forceinline__ void gbar(int* cnt, volatile int* flag, int target) {
    __syncthreads();
    if (threadIdx.x == 0) {
        __threadfence();
        if (atomicAdd(cnt, 1) == target - 1) {
            *cnt = 0;                  // self-reset for next call
            __threadfence();
            *flag = 1;
        } else {
            while (*flag == 0) {}
        }
        __threadfence();
    }
    __syncthreads();
}

__device__ __forceinline__ float fast_sigmoid(float x) {
    return 1.f / (1.f + __expf(-x));
}
__device__ __forceinline__ float fast_tanh(float x) {
    return 2.f / (1.f + __expf(-2.f * x)) - 1.f;
}

__device__ __forceinline__ bool btest(const unsigned* Bm, int x) {
    return (Bm[x >> 5] >> (x & 31)) & 1u;
}

// warp-parallel 2-hop backward BFS; bitmap + list kept in sync; returns size
__device__ int warp_bfs(int t, int seed, unsigned* Bm, int* L, int lane) {
    if (lane == 0) {
        L[0] = seed;
        Bm[seed >> 5] |= 1u << (seed & 31);
    }
    __syncwarp();
    int n = 1, s = 0, e = 1;
#pragma unroll
    for (int hop = 0; hop < 2; hop++) {
        for (int i = s; i < e; i++) {
            int node = L[i];
            int c = g_bcnt[t * NNODES + node];
            if (c > BCAP) c = BCAP;
            int src = (lane < c) ? g_bsrc[(t * NNODES + node) * BCAP + lane]
                                 : (0x40000000 | lane);   // unique sentinel
            bool isnew = (lane < c) && !btest(Bm, src);
            unsigned grp = __match_any_sync(0xffffffffu, src);
            unsigned newm = __ballot_sync(0xffffffffu, isnew);
            bool leader = isnew && ((grp & newm & ((1u << lane) - 1u)) == 0);
            unsigned lm = __ballot_sync(0xffffffffu, leader);
            int pos = n + __popc(lm & ((1u << lane) - 1u));
            if (leader && pos < RCAP) {
                L[pos] = src;
                atomicOr(&Bm[src >> 5], 1u << (src & 31));
            }
            n += __popc(lm);
            if (n > RCAP) n = RCAP;
            __syncwarp();
        }
        s = e; e = n;
    }
    return n;
}

// ---------------------------------------------------------------------------
// L1: scatter edges into buckets -> grid barrier -> warp-per-(t,q) query
__global__ void __launch_bounds__(BLK1, 2)
k_graph(const int* __restrict__ ei) {
    __shared__ unsigned sBmU[WPB1][BW];
    __shared__ unsigned sBmV[WPB1][BW];
    __shared__ int      sLu[WPB1][RCAP];
    __shared__ int      sLv[WPB1][RCAP];

    int tid = threadIdx.x;
    int idx = blockIdx.x * BLK1 + tid;

    if (idx == 0) {                    // resets consumed by L2 / this call
        g_uniq_cnt = 0;
        g_flag2 = 0; g_flag3 = 0;
    }

    // ---- phase A: scatter (t, e) -> bucket of srcs at dst ----
    if (idx < T_SNAP * EQ) {
        int t = idx >> 12;             // EQ = 4096
        int e = idx & (EQ - 1);
        int src = __ldg(&ei[t * 2 * EQ + e]);
        int dst = __ldg(&ei[t * 2 * EQ + EQ + e]);
        int pos = atomicAdd(&g_bcnt[t * NNODES + dst], 1);
        if (pos < BCAP) g_bsrc[(t * NNODES + dst) * BCAP + pos] = src;
    }

    gbar(&g_cnt1, &g_flag1, GRID1);

    // ---- phase B: warp per (t, q) query ----
    int lane = tid & 31;
    int wp   = tid >> 5;
    int gw   = blockIdx.x * WPB1 + wp;
    unsigned* BmU = sBmU[wp];
    unsigned* BmV = sBmV[wp];
    int* Lu = sLu[wp];
    int* Lv = sLv[wp];

    for (int qi = gw; qi < T_SNAP * EQ; qi += NWARP1) {
        int t = qi >> 12;
        int q = qi & (EQ - 1);
        int u = __ldg(&ei[(T_SNAP - 1) * 2 * EQ + q]);
        int v = __ldg(&ei[(T_SNAP - 1) * 2 * EQ + EQ + q]);

        // clear bitmaps
        for (int w = lane; w < BW; w += 32) { BmU[w] = 0u; BmV[w] = 0u; }
        __syncwarp();

        int nu = warp_bfs(t, u, BmU, Lu, lane);
        int nv = warp_bfs(t, v, BmV, Lv, lane);

        float t0 = 0.f, t1 = 0.f, t2 = 0.f;

        // nodes reached from u
        for (int i = 0; i < nu; i++) {
            int node = Lu[i];
            bool nodeInV = btest(BmV, node);
            int c = g_bcnt[t * NNODES + node];
            if (c > BCAP) c = BCAP;
            bool ok = false;
            if (lane < c) {
                int src = g_bsrc[(t * NNODES + node) * BCAP + lane];
                ok = btest(BmU, src) || (nodeInV && btest(BmV, src));
            }
            int d = __popc(__ballot_sync(0xffffffffu, ok));
            float f = (float)d;
            if (f > t0)      { t2 = t1; t1 = t0; t0 = f; }
            else if (f > t1) { t2 = t1; t1 = f; }
            else if (f > t2) { t2 = f; }
        }
        // nodes reached only from v
        for (int i = 0; i < nv; i++) {
            int node = Lv[i];
            if (btest(BmU, node)) continue;    // handled above
            int c = g_bcnt[t * NNODES + node];
            if (c > BCAP) c = BCAP;
            bool ok = false;
            if (lane < c) {
                int src = g_bsrc[(t * NNODES + node) * BCAP + lane];
                ok = btest(BmV, src);
            }
            int d = __popc(__ballot_sync(0xffffffffu, ok));
            float f = (float)d;
            if (f > t0)      { t2 = t1; t1 = t0; t0 = f; }
            else if (f > t1) { t2 = t1; t1 = f; }
            else if (f > t2) { t2 = f; }
        }
        if (lane == 0) {
            g_tops[qi * 3 + 0] = t0;
            g_tops[qi * 3 + 1] = t1;
            g_tops[qi * 3 + 2] = t2;
        }
        __syncwarp();
    }
}

// ---------------------------------------------------------------------------
// L2: gi table + 2-level dedup -> barrier -> GRU per unique -> barrier -> gather
__global__ void __launch_bounds__(BLK2, 2)
k_rnn(const float* __restrict__ Wg,  const float* __restrict__ bg,
      const float* __restrict__ Wih, const float* __restrict__ Whh,
      const float* __restrict__ bih, const float* __restrict__ bhh,
      float* __restrict__ out) {
    __shared__ float sWihT[H][3 * H];   // [kk][j], conflict-free
    __shared__ float sWhhT[H][3 * H];
    __shared__ float sbhh[3 * H];
    __shared__ float sWg[H], sbg[H];
    __shared__ int   bkey[256];         // block-level dedup table
    __shared__ int   bval[256];

    int tid = threadIdx.x;
    int idx = blockIdx.x * BLK2 + tid;

    if (idx == 0) g_flag1 = 0;          // reset L1 barrier flag for next call

    for (int i = tid; i < 3 * H * H; i += BLK2) {
        int j = i / H, kk = i - j * H;
        sWihT[kk][j] = Wih[i];
        sWhhT[kk][j] = Whh[i];
    }
    if (tid < 3 * H) sbhh[tid] = bhh[tid];
    if (tid < H) { sWg[tid] = Wg[tid]; sbg[tid] = bg[tid]; }
    for (int i = tid; i < 256; i += BLK2) bkey[i] = 0;
    __syncthreads();

    // ---- phase A1: gi(v) table ----
    if (idx < 256 * 3 * H) {
        int v = idx / (3 * H);
        int j = idx - v * (3 * H);
        float acc = __ldg(&bih[j]);
        float fv = (float)v;
#pragma unroll
        for (int kk = 0; kk < H; kk++) {
            float xk = fmaxf(fv * sWg[kk] + sbg[kk], 0.f);
            acc += sWihT[kk][j] * xk;
        }
        g_gi[idx] = acc;
    }

    // ---- phase A2: two-level dedup of degree 4-tuples ----
    int  bi = -1;
    bool rep = false;
    int  key = 0;
    float v0 = 0.f, v1 = 0.f, v2 = 0.f, v3 = 0.f;
    if (idx < NB) {
        int b = idx;
        int q = b / 3, p = b - q * 3;
        v0 = g_tops[(0 * EQ + q) * 3 + p];
        v1 = g_tops[(1 * EQ + q) * 3 + p];
        v2 = g_tops[(2 * EQ + q) * 3 + p];
        v3 = g_tops[(3 * EQ + q) * 3 + p];
        int i0 = (int)v0, i1 = (int)v1, i2 = (int)v2, i3 = (int)v3;
        if (i0 > 254 || i1 > 254 || i2 > 254 || i3 > 254)
            key = (int)(0x80000000u | (unsigned)b);        // unique-self
        else
            key = i0 | (i1 << 8) | (i2 << 16) | (i3 << 24) | 0x40000000;
        // block-level insert
        unsigned p2 = ((unsigned)key * 2654435761u) & 255u;
        for (;;) {
            int old = atomicCAS(&bkey[p2], 0, key);
            if (old == 0)  { rep = true; bi = (int)p2; break; }
            if (old == key) { bi = (int)p2; break; }
            p2 = (p2 + 1) & 255u;
        }
    }
    __syncthreads();
    // block reps resolve globally (few contenders per hot key)
    if (rep) {
        unsigned hsl = ((unsigned)key * 2654435761u) & (HT - 1);
        int slot;
        for (;;) {
            int cur = ((volatile int*)g_htkey)[hsl];
            if (cur == key) { slot = (int)hsl; break; }
            if (cur == 0) {
                int old = atomicCAS(&g_htkey[hsl], 0, key);
                if (old == 0) {
                    g_slotv[hsl] = make_float4(v0, v1, v2, v3);
                    int u = atomicAdd(&g_uniq_cnt, 1);
                    g_uniq[u] = (int)hsl;
                    slot = (int)hsl;
                    break;
                }
                if (old == key) { slot = (int)hsl; break; }
            }
            hsl = (hsl + 1) & (HT - 1);
        }
        bval[bi] = slot;
    }
    __syncthreads();
    if (idx < NB) g_bslot[idx] = bval[bi];

    gbar(&g_cnt2, &g_flag2, GRID2);

    // ---- phase B1: clear bucket counters for next call (consumed already) ----
    for (int i = idx; i < T_SNAP * NNODES; i += NTH2) g_bcnt[i] = 0;

    // ---- phase B2: GRU per unique trajectory (one warp each) ----
    int cnt = g_uniq_cnt;
    int lane = tid & 31;
    int w = blockIdx.x * (BLK2 / 32) + (tid >> 5);
    for (int wg = w; wg < cnt; wg += NWARP2) {
        int slot = g_uniq[wg];
        float4 vv = g_slotv[slot];
        float vs[4] = {vv.x, vv.y, vv.z, vv.w};

        float pr[4], pz[4], pg[4];
#pragma unroll
        for (int t = 0; t < T_SNAP; t++) {
            int iv = (int)vs[t];
            if (iv >= 0 && iv < 256) {
                const float* gp = &g_gi[iv * 3 * H];
                pr[t] = gp[lane];
                pz[t] = gp[H + lane];
                pg[t] = gp[2 * H + lane];
            } else {   // rare exact fallback
                float x = fmaxf(vs[t] * sWg[lane] + sbg[lane], 0.f);
                float ar = __ldg(&bih[lane]);
                float az = __ldg(&bih[H + lane]);
                float ag = __ldg(&bih[2 * H + lane]);
                for (int kk = 0; kk < H; kk++) {
                    float xk = __shfl_sync(0xffffffffu, x, kk);
                    ar += sWihT[kk][lane]         * xk;
                    az += sWihT[kk][H + lane]     * xk;
                    ag += sWihT[kk][2 * H + lane] * xk;
                }
                pr[t] = ar; pz[t] = az; pg[t] = ag;
            }
        }

        float h = 0.f;
#pragma unroll
        for (int t = 0; t < T_SNAP; t++) {
            float hr = sbhh[lane], hz = sbhh[H + lane], hg = sbhh[2 * H + lane];
#pragma unroll
            for (int kk = 0; kk < H; kk++) {
                float hk = __shfl_sync(0xffffffffu, h, kk);
                hr += sWhhT[kk][lane]         * hk;
                hz += sWhhT[kk][H + lane]     * hk;
                hg += sWhhT[kk][2 * H + lane] * hk;
            }
            float r = fast_sigmoid(pr[t] + hr);
            float z = fast_sigmoid(pz[t] + hz);
            float n = fast_tanh(pg[t] + r * hg);
            h = (1.f - z) * n + z * h;
        }
        g_uh[slot * H + lane] = h;
        if (lane == 0) g_htkey[slot] = 0;   // reset for next call
    }

    gbar(&g_cnt3, &g_flag3, GRID2);

    // ---- phase C: parallel coalesced gather to output ----
    for (int i = idx; i < NB * H; i += NTH2) {
        int b = i >> 5;
        int j = i & (H - 1);
        out[i] = g_uh[g_bslot[b] * H + j];
    }
}

// ---------------------------------------------------------------------------
extern "C" void kernel_launch(void* const* d_in, const int* in_sizes, int n_in,
                              void* d_out, int out_size) {
    const int*   ei  = (const int*)d_in[0];
    const float* Wg  = (const float*)d_in[1];
    const float* bg  = (const float*)d_in[2];
    const float* Wih = (const float*)d_in[3];
    const float* Whh = (const float*)d_in[4];
    const float* bih = (const float*)d_in[5];
    const float* bhh = (const float*)d_in[6];
    float* out = (float*)d_out;

    k_graph<<<GRID1, BLK1>>>(ei);
    k_rnn  <<<GRID2, BLK2>>>(Wg, bg, Wih, Whh, bih, bhh, out);
}

// round 8
// speedup vs baseline: 1.0898x; 1.0898x over previous
#include <cuda_runtime.h>
#include <math.h>

#define T_SNAP 4
#define EQ     4096
#define NNODES 8192
#define H      32
#define BCAP   32                // in-edge bucket capacity per (t, node)
#define RCAP   128               // per-query reach-set capacity
#define NQ     (T_SNAP * EQ)     // 16384 queries
#define NB     (EQ * 3)          // pooled nodes (GRU batch)

#define GRID1  296               // 2 blocks/SM, all-resident (barrier-safe)
#define BLK1   256
#define NTH1   (GRID1 * BLK1)    // 75776

#define GRID2  192               // no barrier: any geometry; 1536 warps
#define BLK2   256
#define NWARP2 (GRID2 * (BLK2 / 32))

// Scratch (static device globals, zero-initialized; every call restores zeros)
__device__ int    g_bcnt[T_SNAP * NNODES];
__device__ int    g_bsrc[T_SNAP * NNODES * BCAP];
__device__ float  g_tops[NQ * 3];
__device__ float  g_gi[256 * 3 * H];       // gi(v): 256 degrees x (3H), bih folded
__device__ int    g_cnt1;                  // barrier arrive counter (self-reset)
__device__ volatile int g_flag1;           // barrier release flag (reset by k2)

__device__ __forceinline__ float fast_sigmoid(float x) {
    return 1.f / (1.f + __expf(-x));
}
__device__ __forceinline__ float fast_tanh(float x) {
    return 2.f / (1.f + __expf(-2.f * x)) - 1.f;
}

__device__ __forceinline__ bool in_list(const int* l, int n, int x) {
    for (int i = 0; i < n; i++)
        if (l[i] == x) return true;
    return false;
}

// 2-hop backward BFS from seed within snapshot t; returns set size
__device__ __forceinline__ int bfs2(int t, int seed, int* R) {
    R[0] = seed;
    int n = 1, s = 0, e = 1;
#pragma unroll
    for (int hop = 0; hop < 2; hop++) {
        for (int i = s; i < e; i++) {
            int node = R[i];
            int c = g_bcnt[t * NNODES + node];
            if (c > BCAP) c = BCAP;
            const int* b = &g_bsrc[(t * NNODES + node) * BCAP];
            for (int j = 0; j < c; j++) {
                int src = b[j];
                if (!in_list(R, n, src) && n < RCAP) R[n++] = src;
            }
        }
        s = e; e = n;
    }
    return n;
}

// ---------------------------------------------------------------------------
// k1: (scatter edges + gi table) -> grid barrier -> thread-per-(t,q) query
__global__ void __launch_bounds__(BLK1, 2)
k_graph(const int* __restrict__ ei,
        const float* __restrict__ Wg,  const float* __restrict__ bg,
        const float* __restrict__ Wih, const float* __restrict__ bih) {
    int idx = blockIdx.x * BLK1 + threadIdx.x;

    // ---- phase A1: scatter (t, e) -> bucket of srcs at dst ----
    if (idx < NQ) {
        int t = idx >> 12;             // EQ = 4096
        int e = idx & (EQ - 1);
        int src = __ldg(&ei[t * 2 * EQ + e]);
        int dst = __ldg(&ei[t * 2 * EQ + EQ + e]);
        int pos = atomicAdd(&g_bcnt[t * NNODES + dst], 1);
        if (pos < BCAP) g_bsrc[(t * NNODES + dst) * BCAP + pos] = src;
    }
    // ---- phase A2: gi(v) table (depends only on weights) ----
    // gi[v*96 + j] = bih[j] + sum_k Wih[j,k] * relu(v*Wg[k] + bg[k])
    else if (idx < NQ + 256 * 3 * H) {
        int gidx = idx - NQ;
        int v = gidx / (3 * H);
        int j = gidx - v * (3 * H);
        float acc = __ldg(&bih[j]);
        float fv = (float)v;
#pragma unroll
        for (int kk = 0; kk < H; kk++) {
            float xk = fmaxf(fv * __ldg(&Wg[kk]) + __ldg(&bg[kk]), 0.f);
            acc += __ldg(&Wih[j * H + kk]) * xk;
        }
        g_gi[gidx] = acc;
    }

    // ---- grid barrier (flag-based; flag reset by k2) ----
    __syncthreads();
    if (threadIdx.x == 0) {
        __threadfence();
        if (atomicAdd(&g_cnt1, 1) == GRID1 - 1) {
            g_cnt1 = 0;
            __threadfence();
            g_flag1 = 1;
        } else {
            while (g_flag1 == 0) {}
        }
        __threadfence();
    }
    __syncthreads();

    // ---- phase B: thread-per-query, strided over the grid for SM balance ----
    if ((idx & 3) != 0) return;
    int qi = idx >> 2;
    if (qi >= NQ) return;
    int t = qi >> 12;
    int q = qi & (EQ - 1);
    int u = __ldg(&ei[(T_SNAP - 1) * 2 * EQ + q]);
    int v = __ldg(&ei[(T_SNAP - 1) * 2 * EQ + EQ + q]);

    int Ru[RCAP], Rv[RCAP];
    int nu = bfs2(t, u, Ru);
    int nv = bfs2(t, v, Rv);

    float t0 = 0.f, t1 = 0.f, t2 = 0.f;
    for (int pass = 0; pass < 2; pass++) {
        const int* L = pass ? Rv : Ru;
        int nL = pass ? nv : nu;
        for (int i = 0; i < nL; i++) {
            int node = L[i];
            bool inRu, inRv;
            if (pass == 0) {
                inRu = true;
                inRv = in_list(Rv, nv, node);
            } else {
                inRu = in_list(Ru, nu, node);
                if (inRu) continue;        // handled in pass 0
                inRv = true;
            }
            int c = g_bcnt[t * NNODES + node];
            if (c > BCAP) c = BCAP;
            const int* b = &g_bsrc[(t * NNODES + node) * BCAP];
            int d = 0;
            for (int j = 0; j < c; j++) {
                int src = b[j];
                bool su = inRu && in_list(Ru, nu, src);
                bool sv = inRv && in_list(Rv, nv, src);
                if (su || sv) d++;
            }
            float f = (float)d;
            if (f > t0)      { t2 = t1; t1 = t0; t0 = f; }
            else if (f > t1) { t2 = t1; t1 = f; }
            else if (f > t2) { t2 = f; }
        }
    }
    g_tops[qi * 3 + 0] = t0;
    g_tops[qi * 3 + 1] = t1;
    g_tops[qi * 3 + 2] = t2;
}

// ---------------------------------------------------------------------------
// k2: GRU warp-per-pooled-node, direct output; no barriers, no dedup.
// Also clears bucket counters and the k1 barrier flag for the next call.
__global__ void __launch_bounds__(BLK2)
k_rnn(const float* __restrict__ Wg,  const float* __restrict__ bg,
      const float* __restrict__ Wih, const float* __restrict__ Whh,
      const float* __restrict__ bih, const float* __restrict__ bhh,
      float* __restrict__ out) {
    __shared__ float sWihT[H][3 * H];   // [kk][j], conflict-free (fallback path)
    __shared__ float sWhhT[H][3 * H];
    __shared__ float sbhh[3 * H];
    __shared__ float sWg[H], sbg[H];

    int tid = threadIdx.x;
    int idx = blockIdx.x * BLK2 + tid;

    if (idx == 0) g_flag1 = 0;          // reset k1 barrier flag for next call

    // clear bucket counters for next call (queries already consumed them)
    if (idx < T_SNAP * NNODES) g_bcnt[idx] = 0;

    for (int i = tid; i < 3 * H * H; i += BLK2) {
        int j = i / H, kk = i - j * H;
        sWihT[kk][j] = Wih[i];
        sWhhT[kk][j] = Whh[i];
    }
    if (tid < 3 * H) sbhh[tid] = bhh[tid];
    if (tid < H) { sWg[tid] = Wg[tid]; sbg[tid] = bg[tid]; }
    __syncthreads();

    int lane = tid & 31;
    int w = blockIdx.x * (BLK2 / 32) + (tid >> 5);
    for (int b = w; b < NB; b += NWARP2) {
        int q = b / 3, p = b - q * 3;

        // input-side gates for all 4 steps via gi(v) table (coalesced rows)
        float pr[4], pz[4], pg[4];
#pragma unroll
        for (int t = 0; t < T_SNAP; t++) {
            float vt = g_tops[((t << 12) + q) * 3 + p];   // t*EQ + q
            int iv = (int)vt;
            if (iv >= 0 && iv < 256) {
                const float* gp = &g_gi[iv * 3 * H];
                pr[t] = gp[lane];
                pz[t] = gp[H + lane];
                pg[t] = gp[2 * H + lane];
            } else {   // rare exact fallback: compute from weights
                float x = fmaxf(vt * sWg[lane] + sbg[lane], 0.f);
                float ar = __ldg(&bih[lane]);
                float az = __ldg(&bih[H + lane]);
                float ag = __ldg(&bih[2 * H + lane]);
                for (int kk = 0; kk < H; kk++) {
                    float xk = __shfl_sync(0xffffffffu, x, kk);
                    ar += sWihT[kk][lane]         * xk;
                    az += sWihT[kk][H + lane]     * xk;
                    ag += sWihT[kk][2 * H + lane] * xk;
                }
                pr[t] = ar; pz[t] = az; pg[t] = ag;
            }
        }

        float h = 0.f;
#pragma unroll
        for (int t = 0; t < T_SNAP; t++) {
            float hr = sbhh[lane], hz = sbhh[H + lane], hg = sbhh[2 * H + lane];
#pragma unroll
            for (int kk = 0; kk < H; kk++) {
                float hk = __shfl_sync(0xffffffffu, h, kk);
                hr += sWhhT[kk][lane]         * hk;
                hz += sWhhT[kk][H + lane]     * hk;
                hg += sWhhT[kk][2 * H + lane] * hk;
            }
            float r = fast_sigmoid(pr[t] + hr);
            float z = fast_sigmoid(pz[t] + hz);
            float n = fast_tanh(pg[t] + r * hg);
            h = (1.f - z) * n + z * h;
        }
        out[b * H + lane] = h;
    }
}

// ---------------------------------------------------------------------------
extern "C" void kernel_launch(void* const* d_in, const int* in_sizes, int n_in,
                              void* d_out, int out_size) {
    const int*   ei  = (const int*)d_in[0];
    const float* Wg  = (const float*)d_in[1];
    const float* bg  = (const float*)d_in[2];
    const float* Wih = (const float*)d_in[3];
    const float* Whh = (const float*)d_in[4];
    const float* bih = (const float*)d_in[5];
    const float* bhh = (const float*)d_in[6];
    float* out = (float*)d_out;

    k_graph<<<GRID1, BLK1>>>(ei, Wg, bg, Wih, bih);
    k_rnn  <<<GRID2, BLK2>>>(Wg, bg, Wih, Whh, bih, bhh, out);
}